// round 3
// baseline (speedup 1.0000x reference)
#include <cuda_runtime.h>
#include <cuda_bf16.h>
#include <math.h>

// Problem constants (shapes are fixed by the dataset).
#define NKV   32768
#define NQ    4096
#define CDIM  256
#define KSEL  100
#define NT    512   // threads per block

struct Smem {
    unsigned int keys[NKV];   // 128 KB: ordered-uint d^2 keys
    float        qv[CDIM];    // q_feat row
    float        attn[128];   // logits -> softmax weights
    int          ids[128];    // selected neighbor indices (unordered)
    unsigned int hist[256];   // radix histogram
    int          warpsum[8];
    int          red_min[NT / 32];
    float        red1[8];
    float        red2[8];
    int          s_cnt, s_bucket, s_kneed, s_m;
    float        s_sum, s_sumsq;
};

__global__ __launch_bounds__(NT, 1)
void sparse_attn_kernel(const float* __restrict__ q_feat,
                        const float* __restrict__ k_feat,
                        const float* __restrict__ v_feat,
                        const float* __restrict__ q_pos,
                        const float* __restrict__ k_pos,
                        const float* __restrict__ gamma,
                        const float* __restrict__ beta,
                        float* __restrict__ out)
{
    extern __shared__ unsigned char smem_raw[];
    Smem* sm = reinterpret_cast<Smem*>(smem_raw);
    const int tid  = threadIdx.x;
    const int lane = tid & 31;
    const int warp = tid >> 5;
    const int q    = blockIdx.x;

    // ------------------------------------------------------------------
    // Phase 1: distance keys.  d2 = |q|^2 + |k|^2 - 2 q.k  (ref formula),
    // clamp to 0; positive floats are monotone as uint bits.
    // ------------------------------------------------------------------
    const float qx = q_pos[3 * q + 0];
    const float qy = q_pos[3 * q + 1];
    const float qz = q_pos[3 * q + 2];
    const float sq = qx * qx + qy * qy + qz * qz;

    for (int i = tid; i < NKV; i += NT) {
        const float kx = k_pos[3 * i + 0];
        const float ky = k_pos[3 * i + 1];
        const float kz = k_pos[3 * i + 2];
        const float sk  = kx * kx + ky * ky + kz * kz;
        const float dot = qx * kx + qy * ky + qz * kz;
        float d2 = sq + sk - 2.0f * dot;
        d2 = fmaxf(d2, 0.0f);
        sm->keys[i] = __float_as_uint(d2);
    }
    if (tid == 0) sm->s_kneed = KSEL;
    __syncthreads();

    // ------------------------------------------------------------------
    // Phase 2: exact radix select of the KSEL-th smallest key.
    // 4 passes x 8 bits, MSB first.  After the loop:
    //   T       = KSEL-th smallest key value
    //   s_kneed = number of ties at T that belong in the top-KSEL
    // ------------------------------------------------------------------
    unsigned prefval = 0u, prefmask = 0u;
    #pragma unroll
    for (int pass = 0; pass < 4; ++pass) {
        const int shift = 24 - 8 * pass;
        const int kcur  = sm->s_kneed;
        if (tid < 256) sm->hist[tid] = 0u;
        __syncthreads();

        for (int i = tid; i < NKV; i += NT) {
            const unsigned key = sm->keys[i];
            const bool ok = ((key & prefmask) == prefval);
            const unsigned act = __ballot_sync(0xffffffffu, ok);
            if (ok) {
                const unsigned b = (key >> shift) & 0xFFu;
                const unsigned peers = __match_any_sync(act, b);
                if ((__ffs(peers) - 1) == lane)
                    atomicAdd(&sm->hist[b], (unsigned)__popc(peers));
            }
        }
        __syncthreads();

        // 256-bin inclusive scan (8 warps) + bucket pick.
        int v = 0, incl = 0;
        if (tid < 256) {
            v = (int)sm->hist[tid];
            incl = v;
            #pragma unroll
            for (int o = 1; o < 32; o <<= 1) {
                int y = __shfl_up_sync(0xffffffffu, incl, o);
                if (lane >= o) incl += y;
            }
            if (lane == 31) sm->warpsum[tid >> 5] = incl;
        }
        __syncthreads();
        if (tid < 8) {
            int x = sm->warpsum[tid];
            #pragma unroll
            for (int o = 1; o < 8; o <<= 1) {
                int y = __shfl_up_sync(0xffu, x, o);
                if (tid >= o) x += y;
            }
            sm->warpsum[tid] = x;
        }
        __syncthreads();
        if (tid < 256) {
            const int w   = tid >> 5;
            const int tot = incl + (w ? sm->warpsum[w - 1] : 0);
            const int exc = tot - v;
            if (exc < kcur && tot >= kcur) {   // exactly one thread true
                sm->s_bucket = tid;
                sm->s_kneed  = kcur - exc;
            }
        }
        __syncthreads();
        prefval  |= ((unsigned)sm->s_bucket) << shift;
        prefmask |= 0xFFu << shift;
        __syncthreads();
    }
    const unsigned T = prefval;

    // ------------------------------------------------------------------
    // Phase 3: gather the 100 selected indices.
    //   keys < T  -> always selected (order irrelevant: softmax is
    //                permutation invariant over neighbors)
    //   keys == T -> take the s_kneed smallest indices (jax top_k stability)
    // ------------------------------------------------------------------
    if (tid == 0) sm->s_cnt = 0;
    __syncthreads();
    for (int i = tid; i < NKV; i += NT) {
        if (sm->keys[i] < T) {
            const int p = atomicAdd(&sm->s_cnt, 1);
            sm->ids[p] = i;
        }
    }
    __syncthreads();
    const int base = sm->s_cnt;      // == KSEL - ties
    const int ties = sm->s_kneed;    // >= 1
    int last = -1;
    for (int t2 = 0; t2 < ties; ++t2) {
        int local = 0x7fffffff;
        for (int i = tid; i < NKV; i += NT)
            if (sm->keys[i] == T && i > last) local = min(local, i);
        #pragma unroll
        for (int o = 16; o; o >>= 1)
            local = min(local, __shfl_xor_sync(0xffffffffu, local, o));
        if (lane == 0) sm->red_min[warp] = local;
        __syncthreads();
        if (tid == 0) {
            int m = 0x7fffffff;
            #pragma unroll
            for (int w = 0; w < NT / 32; ++w) m = min(m, sm->red_min[w]);
            sm->ids[base + t2] = m;
            sm->s_m = m;
        }
        __syncthreads();
        last = sm->s_m;
        __syncthreads();
    }

    // ------------------------------------------------------------------
    // Phase 4: attention.  logits[n] = (q . k_feat[id[n]]) * C^-0.5
    // One warp per neighbor (round robin), coalesced 1 KB row reads (L2-hot).
    // ------------------------------------------------------------------
    if (tid < CDIM) sm->qv[tid] = q_feat[q * CDIM + tid];
    __syncthreads();

    for (int n = warp; n < KSEL; n += NT / 32) {
        const float* kr = k_feat + (long)sm->ids[n] * CDIM;
        float s = 0.f;
        #pragma unroll
        for (int c = lane; c < CDIM; c += 32) s = fmaf(sm->qv[c], kr[c], s);
        #pragma unroll
        for (int o = 16; o; o >>= 1) s += __shfl_xor_sync(0xffffffffu, s, o);
        if (lane == 0) sm->attn[n] = s * 0.0625f;   // C^-0.5 = 1/16
    }
    __syncthreads();

    // softmax over 100 logits (warp 0)
    if (warp == 0) {
        float m = -1e30f;
        for (int n = lane; n < KSEL; n += 32) m = fmaxf(m, sm->attn[n]);
        #pragma unroll
        for (int o = 16; o; o >>= 1) m = fmaxf(m, __shfl_xor_sync(0xffffffffu, m, o));
        float ssum = 0.f;
        for (int n = lane; n < KSEL; n += 32) {
            const float e = expf(sm->attn[n] - m);
            sm->attn[n] = e;
            ssum += e;
        }
        #pragma unroll
        for (int o = 16; o; o >>= 1) ssum += __shfl_xor_sync(0xffffffffu, ssum, o);
        const float inv = 1.f / ssum;
        for (int n = lane; n < KSEL; n += 32) sm->attn[n] *= inv;
    }
    __syncthreads();

    // ------------------------------------------------------------------
    // Phase 5: x[c] = sum_n attn[n] * v_feat[id[n]][c];  y = 2x
    // (res_feat.at[arange].set(x) fully overwrites -> res == x -> y = 2x)
    // Then LayerNorm over C with gamma/beta.
    // ------------------------------------------------------------------
    float y = 0.f;
    if (tid < CDIM) {
        float acc = 0.f;
        #pragma unroll 4
        for (int n = 0; n < KSEL; ++n)
            acc = fmaf(sm->attn[n], v_feat[(long)sm->ids[n] * CDIM + tid], acc);
        y = 2.0f * acc;
        float s1 = y, s2 = y * y;
        #pragma unroll
        for (int o = 16; o; o >>= 1) {
            s1 += __shfl_xor_sync(0xffffffffu, s1, o);
            s2 += __shfl_xor_sync(0xffffffffu, s2, o);
        }
        if (lane == 0) { sm->red1[warp] = s1; sm->red2[warp] = s2; }
    }
    __syncthreads();
    if (tid == 0) {
        float a = 0.f, b = 0.f;
        #pragma unroll
        for (int w = 0; w < 8; ++w) { a += sm->red1[w]; b += sm->red2[w]; }
        sm->s_sum = a; sm->s_sumsq = b;
    }
    __syncthreads();
    if (tid < CDIM) {
        const float mean = sm->s_sum * (1.0f / CDIM);
        const float var  = sm->s_sumsq * (1.0f / CDIM) - mean * mean;
        const float r    = rsqrtf(var + 1e-5f);
        out[q * CDIM + tid] = (y - mean) * r * gamma[tid] + beta[tid];
    }
}

extern "C" void kernel_launch(void* const* d_in, const int* in_sizes, int n_in,
                              void* d_out, int out_size)
{
    // metadata order: res_feat, q_feat, k_feat, v_feat, q_pos, k_pos, gamma, beta
    // res_feat (d_in[0]) is mathematically dead: full scatter overwrite -> y = 2x.
    const float* q_feat = (const float*)d_in[1];
    const float* k_feat = (const float*)d_in[2];
    const float* v_feat = (const float*)d_in[3];
    const float* q_pos  = (const float*)d_in[4];
    const float* k_pos  = (const float*)d_in[5];
    const float* gamma  = (const float*)d_in[6];
    const float* beta   = (const float*)d_in[7];
    float* out = (float*)d_out;

    (void)in_sizes; (void)n_in; (void)out_size;

    cudaFuncSetAttribute(sparse_attn_kernel,
                         cudaFuncAttributeMaxDynamicSharedMemorySize,
                         (int)sizeof(Smem));
    sparse_attn_kernel<<<NQ, NT, sizeof(Smem)>>>(
        q_feat, k_feat, v_feat, q_pos, k_pos, gamma, beta, out);
}

// round 4
// speedup vs baseline: 2.9629x; 2.9629x over previous
#include <cuda_runtime.h>
#include <cuda_bf16.h>
#include <math.h>

#define NKV   32768
#define NQ    4096
#define CDIM  256
#define KSEL  100
#define NT    512
#define QB    2
#define CAP   2048

struct Smem {
    uint2    cand[QB][CAP];    // 32 KB  {key, idx}
    float    qv[QB][CDIM];     // 2 KB
    float    attn[QB][128];    // 1 KB
    int      ids[QB][128];     // 1 KB
    unsigned hist[QB][256];    // 2 KB
    int      warpsum[8];
    int      red_min[16];
    float    red1[16], red2[16];
    int      cnt_low[QB], cnt_c[QB];
    int      s_bucket, s_kneed, s_m;
    float    s_sum[QB], s_sumsq[QB];
};

// Deterministic key: identical fmaf chain in every scan -> bit-identical keys.
__device__ __forceinline__ unsigned dist_key(float kx, float ky, float kz,
                                             float qx, float qy, float qz,
                                             float sqn) {
    const float sk  = fmaf(kx, kx, fmaf(ky, ky, kz * kz));
    const float dot = fmaf(qx, kx, fmaf(qy, ky, qz * kz));
    const float d2  = fmaxf(fmaf(-2.0f, dot, sqn + sk), 0.0f);
    return __float_as_uint(d2);
}

// All 512 threads enter. Picks the bucket containing the kcur-th smallest,
// broadcasts via sm->s_bucket / sm->s_kneed (read after return).
__device__ __forceinline__ void pick_bucket(Smem* sm, const unsigned* hist,
                                            int kcur, int tid, int lane) {
    int v = 0, incl = 0;
    if (tid < 256) {
        v = (int)hist[tid];
        incl = v;
        #pragma unroll
        for (int o = 1; o < 32; o <<= 1) {
            int y = __shfl_up_sync(0xffffffffu, incl, o);
            if (lane >= o) incl += y;
        }
        if (lane == 31) sm->warpsum[tid >> 5] = incl;
    }
    __syncthreads();
    if (tid < 8) {
        int x = sm->warpsum[tid];
        #pragma unroll
        for (int o = 1; o < 8; o <<= 1) {
            int y = __shfl_up_sync(0xffu, x, o);
            if (tid >= o) x += y;
        }
        sm->warpsum[tid] = x;
    }
    __syncthreads();
    if (tid < 256) {
        const int w   = tid >> 5;
        const int tot = incl + (w ? sm->warpsum[w - 1] : 0);
        const int exc = tot - v;
        if (exc < kcur && tot >= kcur) {   // exactly one thread true
            sm->s_bucket = tid;
            sm->s_kneed  = kcur - exc;
        }
    }
    __syncthreads();
}

__global__ __launch_bounds__(NT, 4)
void sparse_attn_kernel(const float* __restrict__ q_feat,
                        const float* __restrict__ k_feat,
                        const float* __restrict__ v_feat,
                        const float* __restrict__ q_pos,
                        const float* __restrict__ k_pos,
                        const float* __restrict__ gamma,
                        const float* __restrict__ beta,
                        float* __restrict__ out)
{
    extern __shared__ unsigned char smem_raw[];
    Smem* sm = reinterpret_cast<Smem*>(smem_raw);
    const int tid  = threadIdx.x;
    const int lane = tid & 31;
    const int warp = tid >> 5;
    const int qbase = blockIdx.x * QB;

    // query positions (uniform broadcast loads)
    float qx[QB], qy[QB], qz[QB], sqn[QB];
    #pragma unroll
    for (int qi = 0; qi < QB; ++qi) {
        qx[qi] = q_pos[3 * (qbase + qi) + 0];
        qy[qi] = q_pos[3 * (qbase + qi) + 1];
        qz[qi] = q_pos[3 * (qbase + qi) + 2];
        sqn[qi] = fmaf(qx[qi], qx[qi], fmaf(qy[qi], qy[qi], qz[qi] * qz[qi]));
    }

    if (tid < 256) { sm->hist[0][tid] = 0u; sm->hist[1][tid] = 0u; }
    if (tid == 0) {
        sm->cnt_low[0] = sm->cnt_low[1] = 0;
        sm->cnt_c[0]   = sm->cnt_c[1]   = 0;
    }
    __syncthreads();

    // ---------------- Phase 1: top-byte histogram (on-the-fly keys) --------
    for (int i = tid; i < NKV; i += NT) {       // NKV % NT == 0: fully converged
        const float kx = k_pos[3 * i + 0];
        const float ky = k_pos[3 * i + 1];
        const float kz = k_pos[3 * i + 2];
        #pragma unroll
        for (int qi = 0; qi < QB; ++qi) {
            const unsigned b = dist_key(kx, ky, kz, qx[qi], qy[qi], qz[qi], sqn[qi]) >> 24;
            const unsigned peers = __match_any_sync(0xffffffffu, b);
            if ((__ffs(peers) - 1) == lane)
                atomicAdd(&sm->hist[qi][b], (unsigned)__popc(peers));
        }
    }
    __syncthreads();

    // ---------------- Phase 2: pick byte-0 bucket per query ----------------
    int rb0[QB], rkn[QB];
    #pragma unroll
    for (int qi = 0; qi < QB; ++qi) {
        pick_bucket(sm, sm->hist[qi], KSEL, tid, lane);
        rb0[qi] = sm->s_bucket;     // all threads read after internal sync
        rkn[qi] = sm->s_kneed;
        __syncthreads();
    }

    // ---------------- Phase 3: compaction scan ------------------------------
    for (int i = tid; i < NKV; i += NT) {
        const float kx = k_pos[3 * i + 0];
        const float ky = k_pos[3 * i + 1];
        const float kz = k_pos[3 * i + 2];
        #pragma unroll
        for (int qi = 0; qi < QB; ++qi) {
            const unsigned key = dist_key(kx, ky, kz, qx[qi], qy[qi], qz[qi], sqn[qi]);
            const int b = (int)(key >> 24);
            if (b < rb0[qi]) {
                const int p = atomicAdd(&sm->cnt_low[qi], 1);   // < KSEL guaranteed
                sm->ids[qi][p] = i;
            } else if (b == rb0[qi]) {
                const int p = atomicAdd(&sm->cnt_c[qi], 1);
                if (p < CAP) sm->cand[qi][p] = make_uint2(key, (unsigned)i);
            }
        }
    }
    __syncthreads();

    // ---------------- Phase 4: refine within candidates ---------------------
    #pragma unroll
    for (int qi = 0; qi < QB; ++qi) {
        const int nc = sm->cnt_c[qi];
        unsigned prefval  = ((unsigned)rb0[qi]) << 24;
        unsigned prefmask = 0xFF000000u;
        int kneed = rkn[qi];

        if (nc <= CAP) {
            // ---- 3 radix passes over <=2048 candidates ----
            for (int pass = 1; pass < 4; ++pass) {
                const int shift = 24 - 8 * pass;
                if (tid < 256) sm->hist[0][tid] = 0u;
                __syncthreads();
                const int nIter = (nc + NT - 1) / NT;
                for (int it = 0; it < nIter; ++it) {
                    const int j = tid + it * NT;
                    const bool in = (j < nc);
                    const unsigned key = in ? sm->cand[qi][j].x : 0xffffffffu;
                    const bool ok = in && ((key & prefmask) == prefval);
                    const unsigned act = __ballot_sync(0xffffffffu, ok);
                    if (ok) {
                        const unsigned b = (key >> shift) & 0xFFu;
                        const unsigned peers = __match_any_sync(act, b);
                        if ((__ffs(peers) - 1) == lane)
                            atomicAdd(&sm->hist[0][b], (unsigned)__popc(peers));
                    }
                }
                __syncthreads();
                pick_bucket(sm, sm->hist[0], kneed, tid, lane);
                prefval  |= ((unsigned)sm->s_bucket) << shift;
                kneed     = sm->s_kneed;
                prefmask |= 0xFFu << shift;
                __syncthreads();
            }
            const unsigned T = prefval;
            // strictly-less keys among candidates -> ids (order irrelevant)
            for (int j = tid; j < nc; j += NT) {
                const uint2 c = sm->cand[qi][j];
                if (c.x < T) {
                    const int p = atomicAdd(&sm->cnt_low[qi], 1);
                    sm->ids[qi][p] = (int)c.y;
                }
            }
            __syncthreads();
            // ties at T: kneed smallest indices (jax top_k stability)
            const int base = sm->cnt_low[qi];
            int last = -1;
            for (int t2 = 0; t2 < kneed; ++t2) {
                int local = 0x7fffffff;
                for (int j = tid; j < nc; j += NT) {
                    const uint2 c = sm->cand[qi][j];
                    if (c.x == T && (int)c.y > last) local = min(local, (int)c.y);
                }
                #pragma unroll
                for (int o = 16; o; o >>= 1)
                    local = min(local, __shfl_xor_sync(0xffffffffu, local, o));
                if (lane == 0) sm->red_min[warp] = local;
                __syncthreads();
                if (tid == 0) {
                    int m = 0x7fffffff;
                    #pragma unroll
                    for (int w = 0; w < NT / 32; ++w) m = min(m, sm->red_min[w]);
                    sm->ids[qi][base + t2] = m;
                    sm->s_m = m;
                }
                __syncthreads();
                last = sm->s_m;
                __syncthreads();
            }
        } else {
            // ---- fallback: full rescans (recompute keys). Rare. ----
            for (int pass = 1; pass < 4; ++pass) {
                const int shift = 24 - 8 * pass;
                if (tid < 256) sm->hist[0][tid] = 0u;
                __syncthreads();
                for (int i = tid; i < NKV; i += NT) {
                    const unsigned key = dist_key(k_pos[3*i], k_pos[3*i+1], k_pos[3*i+2],
                                                  qx[qi], qy[qi], qz[qi], sqn[qi]);
                    const bool ok = ((key & prefmask) == prefval);
                    const unsigned act = __ballot_sync(0xffffffffu, ok);
                    if (ok) {
                        const unsigned b = (key >> shift) & 0xFFu;
                        const unsigned peers = __match_any_sync(act, b);
                        if ((__ffs(peers) - 1) == lane)
                            atomicAdd(&sm->hist[0][b], (unsigned)__popc(peers));
                    }
                }
                __syncthreads();
                pick_bucket(sm, sm->hist[0], kneed, tid, lane);
                prefval  |= ((unsigned)sm->s_bucket) << shift;
                kneed     = sm->s_kneed;
                prefmask |= 0xFFu << shift;
                __syncthreads();
            }
            const unsigned T = prefval;
            const unsigned prefbase = ((unsigned)rb0[qi]) << 24;
            for (int i = tid; i < NKV; i += NT) {
                const unsigned key = dist_key(k_pos[3*i], k_pos[3*i+1], k_pos[3*i+2],
                                              qx[qi], qy[qi], qz[qi], sqn[qi]);
                if (key >= prefbase && key < T) {
                    const int p = atomicAdd(&sm->cnt_low[qi], 1);
                    sm->ids[qi][p] = i;
                }
            }
            __syncthreads();
            const int base = sm->cnt_low[qi];
            int last = -1;
            for (int t2 = 0; t2 < kneed; ++t2) {
                int local = 0x7fffffff;
                for (int i = tid; i < NKV; i += NT) {
                    const unsigned key = dist_key(k_pos[3*i], k_pos[3*i+1], k_pos[3*i+2],
                                                  qx[qi], qy[qi], qz[qi], sqn[qi]);
                    if (key == T && i > last) local = min(local, i);
                }
                #pragma unroll
                for (int o = 16; o; o >>= 1)
                    local = min(local, __shfl_xor_sync(0xffffffffu, local, o));
                if (lane == 0) sm->red_min[warp] = local;
                __syncthreads();
                if (tid == 0) {
                    int m = 0x7fffffff;
                    #pragma unroll
                    for (int w = 0; w < NT / 32; ++w) m = min(m, sm->red_min[w]);
                    sm->ids[qi][base + t2] = m;
                    sm->s_m = m;
                }
                __syncthreads();
                last = sm->s_m;
                __syncthreads();
            }
        }
        __syncthreads();
    }

    // ---------------- Phase 5: attention (warps 0-7 -> q0, 8-15 -> q1) ------
    {
        const int qi = tid >> 8;
        const int c  = tid & 255;
        sm->qv[qi][c] = q_feat[(long)(qbase + qi) * CDIM + c];
    }
    __syncthreads();

    const int wq = warp >> 3;
    const int wl = warp & 7;
    for (int n = wl; n < KSEL; n += 8) {
        const float4* kr4 = (const float4*)(k_feat + (long)sm->ids[wq][n] * CDIM);
        const float4* qv4 = (const float4*)sm->qv[wq];
        float s = 0.f;
        #pragma unroll
        for (int c4 = lane; c4 < CDIM / 4; c4 += 32) {
            const float4 a = qv4[c4];
            const float4 b = kr4[c4];
            s = fmaf(a.x, b.x, s); s = fmaf(a.y, b.y, s);
            s = fmaf(a.z, b.z, s); s = fmaf(a.w, b.w, s);
        }
        #pragma unroll
        for (int o = 16; o; o >>= 1) s += __shfl_xor_sync(0xffffffffu, s, o);
        if (lane == 0) sm->attn[wq][n] = s * 0.0625f;   // C^-0.5 = 1/16
    }
    __syncthreads();

    if ((warp & 7) == 0) {              // warp 0 -> q0, warp 8 -> q1
        const int qi = wq;
        float m = -1e30f;
        for (int n = lane; n < KSEL; n += 32) m = fmaxf(m, sm->attn[qi][n]);
        #pragma unroll
        for (int o = 16; o; o >>= 1) m = fmaxf(m, __shfl_xor_sync(0xffffffffu, m, o));
        float ssum = 0.f;
        for (int n = lane; n < KSEL; n += 32) {
            const float e = expf(sm->attn[qi][n] - m);
            sm->attn[qi][n] = e;
            ssum += e;
        }
        #pragma unroll
        for (int o = 16; o; o >>= 1) ssum += __shfl_xor_sync(0xffffffffu, ssum, o);
        const float inv = 1.f / ssum;
        for (int n = lane; n < KSEL; n += 32) sm->attn[qi][n] *= inv;
    }
    __syncthreads();

    // ---------------- Phase 6: x = attn @ V;  y = 2x;  LayerNorm ------------
    {
        const int qi = tid >> 8;
        const int c  = tid & 255;
        float acc = 0.f;
        #pragma unroll 4
        for (int n = 0; n < KSEL; ++n)
            acc = fmaf(sm->attn[qi][n], v_feat[(long)sm->ids[qi][n] * CDIM + c], acc);
        const float y = 2.0f * acc;   // res_feat fully overwritten -> y = 2x

        float s1 = y, s2 = y * y;
        #pragma unroll
        for (int o = 16; o; o >>= 1) {
            s1 += __shfl_xor_sync(0xffffffffu, s1, o);
            s2 += __shfl_xor_sync(0xffffffffu, s2, o);
        }
        if (lane == 0) { sm->red1[warp] = s1; sm->red2[warp] = s2; }
        __syncthreads();
        if ((tid & 255) == 0) {
            float a = 0.f, b = 0.f;
            #pragma unroll
            for (int w = 0; w < 8; ++w) {
                a += sm->red1[qi * 8 + w];
                b += sm->red2[qi * 8 + w];
            }
            sm->s_sum[qi] = a; sm->s_sumsq[qi] = b;
        }
        __syncthreads();
        const float mean = sm->s_sum[qi] * (1.0f / CDIM);
        const float var  = sm->s_sumsq[qi] * (1.0f / CDIM) - mean * mean;
        const float r    = rsqrtf(var + 1e-5f);
        out[(long)(qbase + qi) * CDIM + c] = (y - mean) * r * gamma[c] + beta[c];
    }
}

extern "C" void kernel_launch(void* const* d_in, const int* in_sizes, int n_in,
                              void* d_out, int out_size)
{
    // metadata order: res_feat, q_feat, k_feat, v_feat, q_pos, k_pos, gamma, beta
    // res_feat (d_in[0]) is mathematically dead: full scatter overwrite -> y = 2x.
    const float* q_feat = (const float*)d_in[1];
    const float* k_feat = (const float*)d_in[2];
    const float* v_feat = (const float*)d_in[3];
    const float* q_pos  = (const float*)d_in[4];
    const float* k_pos  = (const float*)d_in[5];
    const float* gamma  = (const float*)d_in[6];
    const float* beta   = (const float*)d_in[7];
    float* out = (float*)d_out;

    (void)in_sizes; (void)n_in; (void)out_size;

    cudaFuncSetAttribute(sparse_attn_kernel,
                         cudaFuncAttributeMaxDynamicSharedMemorySize,
                         (int)sizeof(Smem));
    sparse_attn_kernel<<<NQ / QB, NT, sizeof(Smem)>>>(
        q_feat, k_feat, v_feat, q_pos, k_pos, gamma, beta, out);
}

// round 5
// speedup vs baseline: 4.6678x; 1.5754x over previous
#include <cuda_runtime.h>
#include <cuda_bf16.h>
#include <math.h>

#define NKV   32768
#define NQ    4096
#define CDIM  256
#define KSEL  100
#define NT    512
#define QB    2
#define CAP   2048
#define SSAMP 2048   // sample size for threshold estimation
#define MSEL  32     // take the 32nd-smallest sample key as threshold

struct Smem {
    uint2    cand[QB][CAP];    // 32 KB {key, idx}; overlaid by sample keys first
    float    qv[QB][CDIM];     // 2 KB
    float    attn[QB][128];    // 1 KB
    int      ids[QB][128];     // 1 KB
    unsigned hist[256];        // 1 KB
    int      warpsum[8];
    int      red_min[16];
    float    red1[16], red2[16];
    int      cnt_low[QB], cnt_c[QB];
    int      s_bucket, s_kneed, s_m;
    float    s_sum[QB], s_sumsq[QB];
};

// Canonical key pieces — identical fmaf chains everywhere => bit-identical keys.
__device__ __forceinline__ float k_sk(float kx, float ky, float kz) {
    return fmaf(kx, kx, fmaf(ky, ky, kz * kz));
}
__device__ __forceinline__ float k_dot(float kx, float ky, float kz,
                                       float qx, float qy, float qz) {
    return fmaf(qx, kx, fmaf(qy, ky, qz * kz));
}
__device__ __forceinline__ float k_d2u(float sk, float dot, float sqn) {
    return fmaf(-2.0f, dot, sqn + sk);      // unclamped
}
__device__ __forceinline__ unsigned k_key(float d2u) {
    return __float_as_uint(fmaxf(d2u, 0.0f));
}

// All 512 threads enter. Picks the bucket containing the kcur-th smallest,
// broadcasts via sm->s_bucket / sm->s_kneed (read after return).
__device__ __forceinline__ void pick_bucket(Smem* sm, int kcur, int tid, int lane) {
    int v = 0, incl = 0;
    if (tid < 256) {
        v = (int)sm->hist[tid];
        incl = v;
        #pragma unroll
        for (int o = 1; o < 32; o <<= 1) {
            int y = __shfl_up_sync(0xffffffffu, incl, o);
            if (lane >= o) incl += y;
        }
        if (lane == 31) sm->warpsum[tid >> 5] = incl;
    }
    __syncthreads();
    if (tid < 8) {
        int x = sm->warpsum[tid];
        #pragma unroll
        for (int o = 1; o < 8; o <<= 1) {
            int y = __shfl_up_sync(0xffu, x, o);
            if (tid >= o) x += y;
        }
        sm->warpsum[tid] = x;
    }
    __syncthreads();
    if (tid < 256) {
        const int w   = tid >> 5;
        const int tot = incl + (w ? sm->warpsum[w - 1] : 0);
        const int exc = tot - v;
        if (exc < kcur && tot >= kcur) {   // exactly one thread true
            sm->s_bucket = tid;
            sm->s_kneed  = kcur - exc;
        }
    }
    __syncthreads();
}

__global__ __launch_bounds__(NT, 4)
void sparse_attn_kernel(const float* __restrict__ q_feat,
                        const float* __restrict__ k_feat,
                        const float* __restrict__ v_feat,
                        const float* __restrict__ q_pos,
                        const float* __restrict__ k_pos,
                        const float* __restrict__ gamma,
                        const float* __restrict__ beta,
                        float* __restrict__ out)
{
    extern __shared__ unsigned char smem_raw[];
    Smem* sm = reinterpret_cast<Smem*>(smem_raw);
    const int tid  = threadIdx.x;
    const int lane = tid & 31;
    const int warp = tid >> 5;
    const int qbase = blockIdx.x * QB;

    float qx[QB], qy[QB], qz[QB], sqn[QB];
    #pragma unroll
    for (int qi = 0; qi < QB; ++qi) {
        qx[qi] = q_pos[3 * (qbase + qi) + 0];
        qy[qi] = q_pos[3 * (qbase + qi) + 1];
        qz[qi] = q_pos[3 * (qbase + qi) + 2];
        sqn[qi] = fmaf(qx[qi], qx[qi], fmaf(qy[qi], qy[qi], qz[qi] * qz[qi]));
    }
    if (tid == 0) {
        sm->cnt_low[0] = sm->cnt_low[1] = 0;
        sm->cnt_c[0]   = sm->cnt_c[1]   = 0;
    }

    // ---------------- Phase 0: sample keys (first SSAMP elements, i.i.d.) ---
    unsigned* samp = (unsigned*)&sm->cand[0][0];   // SSAMP per query, overlaid
    for (int j = tid; j < SSAMP; j += NT) {
        const float kx = k_pos[3 * j + 0];
        const float ky = k_pos[3 * j + 1];
        const float kz = k_pos[3 * j + 2];
        const float sk = k_sk(kx, ky, kz);
        #pragma unroll
        for (int qi = 0; qi < QB; ++qi)
            samp[qi * SSAMP + j] =
                k_key(k_d2u(sk, k_dot(kx, ky, kz, qx[qi], qy[qi], qz[qi]), sqn[qi]));
    }
    __syncthreads();

    // ---------------- Phase 1: exact MSEL-th smallest of each sample --------
    float t0f[QB];
    unsigned t0u[QB];
    #pragma unroll
    for (int qi = 0; qi < QB; ++qi) {
        unsigned prefval = 0u, prefmask = 0u;
        int kneed = MSEL;
        #pragma unroll
        for (int pass = 0; pass < 4; ++pass) {
            const int shift = 24 - 8 * pass;
            if (tid < 256) sm->hist[tid] = 0u;
            __syncthreads();
            for (int j = tid; j < SSAMP; j += NT) {     // SSAMP % NT == 0
                const unsigned key = samp[qi * SSAMP + j];
                const bool ok = ((key & prefmask) == prefval);
                const unsigned act = __ballot_sync(0xffffffffu, ok);
                if (ok) {
                    const unsigned b = (key >> shift) & 0xFFu;
                    const unsigned peers = __match_any_sync(act, b);
                    if ((__ffs(peers) - 1) == lane)
                        atomicAdd(&sm->hist[b], (unsigned)__popc(peers));
                }
            }
            __syncthreads();
            pick_bucket(sm, kneed, tid, lane);
            prefval  |= ((unsigned)sm->s_bucket) << shift;
            kneed     = sm->s_kneed;
            prefmask |= 0xFFu << shift;
            __syncthreads();
        }
        t0u[qi] = prefval;                    // uniform across the block
        t0f[qi] = __uint_as_float(prefval);   // >= 0 (keys are clamped)
    }
    __syncthreads();   // done reading samp; cand may now be written

    // ---------------- Phase 2: single full scan, admit d2u <= t0 ------------
    // Unclamped compare is exact: t0 >= 0, so (clamped_key <= t0) <=> (d2u <= t0f).
    for (int i = tid; i < NKV; i += NT) {
        const float kx = k_pos[3 * i + 0];
        const float ky = k_pos[3 * i + 1];
        const float kz = k_pos[3 * i + 2];
        const float sk = k_sk(kx, ky, kz);
        #pragma unroll
        for (int qi = 0; qi < QB; ++qi) {
            const float d2u = k_d2u(sk, k_dot(kx, ky, kz, qx[qi], qy[qi], qz[qi]), sqn[qi]);
            if (d2u <= t0f[qi]) {
                const int p = atomicAdd(&sm->cnt_c[qi], 1);
                if (p < CAP) sm->cand[qi][p] = make_uint2(k_key(d2u), (unsigned)i);
            }
        }
    }
    __syncthreads();

    // ---------------- Phase 3: exact top-KSEL per query ---------------------
    #pragma unroll
    for (int qi = 0; qi < QB; ++qi) {
        const int nc0 = sm->cnt_c[qi];
        unsigned T;
        int kneed;

        if (nc0 >= KSEL && nc0 <= CAP) {
            // ---- refine within <= CAP candidates: full 32-bit radix select --
            const int nc = nc0;
            unsigned prefval = 0u, prefmask = 0u;
            kneed = KSEL;
            #pragma unroll
            for (int pass = 0; pass < 4; ++pass) {
                const int shift = 24 - 8 * pass;
                if (tid < 256) sm->hist[tid] = 0u;
                __syncthreads();
                const int nIter = (nc + NT - 1) / NT;
                for (int it = 0; it < nIter; ++it) {
                    const int j = tid + it * NT;
                    const bool in = (j < nc);
                    const unsigned key = in ? sm->cand[qi][j].x : 0xffffffffu;
                    const bool ok = in && ((key & prefmask) == prefval);
                    const unsigned act = __ballot_sync(0xffffffffu, ok);
                    if (ok) {
                        const unsigned b = (key >> shift) & 0xFFu;
                        const unsigned peers = __match_any_sync(act, b);
                        if ((__ffs(peers) - 1) == lane)
                            atomicAdd(&sm->hist[b], (unsigned)__popc(peers));
                    }
                }
                __syncthreads();
                pick_bucket(sm, kneed, tid, lane);
                prefval  |= ((unsigned)sm->s_bucket) << shift;
                kneed     = sm->s_kneed;
                prefmask |= 0xFFu << shift;
                __syncthreads();
            }
            T = prefval;
            // strictly-less keys -> ids (order irrelevant: softmax perm-invariant)
            for (int j = tid; j < nc; j += NT) {
                const uint2 c = sm->cand[qi][j];
                if (c.x < T) {
                    const int p = atomicAdd(&sm->cnt_low[qi], 1);
                    sm->ids[qi][p] = (int)c.y;
                }
            }
            __syncthreads();
            // ties at T: kneed smallest indices (jax top_k stability)
            const int base = sm->cnt_low[qi];
            int last = -1;
            for (int t2 = 0; t2 < kneed; ++t2) {
                int local = 0x7fffffff;
                for (int j = tid; j < nc; j += NT) {
                    const uint2 c = sm->cand[qi][j];
                    if (c.x == T && (int)c.y > last) local = min(local, (int)c.y);
                }
                #pragma unroll
                for (int o = 16; o; o >>= 1)
                    local = min(local, __shfl_xor_sync(0xffffffffu, local, o));
                if (lane == 0) sm->red_min[warp] = local;
                __syncthreads();
                if (tid == 0) {
                    int m = 0x7fffffff;
                    #pragma unroll
                    for (int w = 0; w < NT / 32; ++w) m = min(m, sm->red_min[w]);
                    sm->ids[qi][base + t2] = m;
                    sm->s_m = m;
                }
                __syncthreads();
                last = sm->s_m;
                __syncthreads();
            }
        } else {
            // ---- fallback: exact full-rescan radix select (rare) ------------
            unsigned prefval = 0u, prefmask = 0u;
            kneed = KSEL;
            for (int pass = 0; pass < 4; ++pass) {
                const int shift = 24 - 8 * pass;
                if (tid < 256) sm->hist[tid] = 0u;
                __syncthreads();
                for (int i = tid; i < NKV; i += NT) {
                    const float kx = k_pos[3 * i + 0];
                    const float ky = k_pos[3 * i + 1];
                    const float kz = k_pos[3 * i + 2];
                    const unsigned key = k_key(k_d2u(k_sk(kx, ky, kz),
                                         k_dot(kx, ky, kz, qx[qi], qy[qi], qz[qi]), sqn[qi]));
                    const bool ok = ((key & prefmask) == prefval);
                    const unsigned act = __ballot_sync(0xffffffffu, ok);
                    if (ok) {
                        const unsigned b = (key >> shift) & 0xFFu;
                        const unsigned peers = __match_any_sync(act, b);
                        if ((__ffs(peers) - 1) == lane)
                            atomicAdd(&sm->hist[b], (unsigned)__popc(peers));
                    }
                }
                __syncthreads();
                pick_bucket(sm, kneed, tid, lane);
                prefval  |= ((unsigned)sm->s_bucket) << shift;
                kneed     = sm->s_kneed;
                prefmask |= 0xFFu << shift;
                __syncthreads();
            }
            T = prefval;
            if (tid == 0) sm->cnt_low[qi] = 0;
            __syncthreads();
            for (int i = tid; i < NKV; i += NT) {
                const float kx = k_pos[3 * i + 0];
                const float ky = k_pos[3 * i + 1];
                const float kz = k_pos[3 * i + 2];
                const unsigned key = k_key(k_d2u(k_sk(kx, ky, kz),
                                     k_dot(kx, ky, kz, qx[qi], qy[qi], qz[qi]), sqn[qi]));
                if (key < T) {
                    const int p = atomicAdd(&sm->cnt_low[qi], 1);
                    sm->ids[qi][p] = i;
                }
            }
            __syncthreads();
            const int base = sm->cnt_low[qi];
            int last = -1;
            for (int t2 = 0; t2 < kneed; ++t2) {
                int local = 0x7fffffff;
                for (int i = tid; i < NKV; i += NT) {
                    const float kx = k_pos[3 * i + 0];
                    const float ky = k_pos[3 * i + 1];
                    const float kz = k_pos[3 * i + 2];
                    const unsigned key = k_key(k_d2u(k_sk(kx, ky, kz),
                                         k_dot(kx, ky, kz, qx[qi], qy[qi], qz[qi]), sqn[qi]));
                    if (key == T && i > last) local = min(local, i);
                }
                #pragma unroll
                for (int o = 16; o; o >>= 1)
                    local = min(local, __shfl_xor_sync(0xffffffffu, local, o));
                if (lane == 0) sm->red_min[warp] = local;
                __syncthreads();
                if (tid == 0) {
                    int m = 0x7fffffff;
                    #pragma unroll
                    for (int w = 0; w < NT / 32; ++w) m = min(m, sm->red_min[w]);
                    sm->ids[qi][base + t2] = m;
                    sm->s_m = m;
                }
                __syncthreads();
                last = sm->s_m;
                __syncthreads();
            }
        }
        __syncthreads();
    }

    // ---------------- Phase 4: attention (warps 0-7 -> q0, 8-15 -> q1) ------
    {
        const int qi = tid >> 8;
        const int c  = tid & 255;
        sm->qv[qi][c] = q_feat[(long)(qbase + qi) * CDIM + c];
    }
    __syncthreads();

    const int wq = warp >> 3;
    const int wl = warp & 7;
    for (int n = wl; n < KSEL; n += 8) {
        const float4* kr4 = (const float4*)(k_feat + (long)sm->ids[wq][n] * CDIM);
        const float4* qv4 = (const float4*)sm->qv[wq];
        float s = 0.f;
        #pragma unroll
        for (int c4 = lane; c4 < CDIM / 4; c4 += 32) {
            const float4 a = qv4[c4];
            const float4 b = kr4[c4];
            s = fmaf(a.x, b.x, s); s = fmaf(a.y, b.y, s);
            s = fmaf(a.z, b.z, s); s = fmaf(a.w, b.w, s);
        }
        #pragma unroll
        for (int o = 16; o; o >>= 1) s += __shfl_xor_sync(0xffffffffu, s, o);
        if (lane == 0) sm->attn[wq][n] = s * 0.0625f;   // C^-0.5 = 1/16
    }
    __syncthreads();

    if ((warp & 7) == 0) {              // warp 0 -> q0, warp 8 -> q1
        const int qi = wq;
        float m = -1e30f;
        for (int n = lane; n < KSEL; n += 32) m = fmaxf(m, sm->attn[qi][n]);
        #pragma unroll
        for (int o = 16; o; o >>= 1) m = fmaxf(m, __shfl_xor_sync(0xffffffffu, m, o));
        float ssum = 0.f;
        for (int n = lane; n < KSEL; n += 32) {
            const float e = expf(sm->attn[qi][n] - m);
            sm->attn[qi][n] = e;
            ssum += e;
        }
        #pragma unroll
        for (int o = 16; o; o >>= 1) ssum += __shfl_xor_sync(0xffffffffu, ssum, o);
        const float inv = 1.f / ssum;
        for (int n = lane; n < KSEL; n += 32) sm->attn[qi][n] *= inv;
    }
    __syncthreads();

    // ---------------- Phase 5: x = attn @ V;  y = 2x;  LayerNorm ------------
    {
        const int qi = tid >> 8;
        const int c  = tid & 255;
        float acc = 0.f;
        #pragma unroll 4
        for (int n = 0; n < KSEL; ++n)
            acc = fmaf(sm->attn[qi][n], v_feat[(long)sm->ids[qi][n] * CDIM + c], acc);
        const float y = 2.0f * acc;   // res_feat fully overwritten -> y = 2x

        float s1 = y, s2 = y * y;
        #pragma unroll
        for (int o = 16; o; o >>= 1) {
            s1 += __shfl_xor_sync(0xffffffffu, s1, o);
            s2 += __shfl_xor_sync(0xffffffffu, s2, o);
        }
        if (lane == 0) { sm->red1[warp] = s1; sm->red2[warp] = s2; }
        __syncthreads();
        if ((tid & 255) == 0) {
            float a = 0.f, b = 0.f;
            #pragma unroll
            for (int w = 0; w < 8; ++w) {
                a += sm->red1[qi * 8 + w];
                b += sm->red2[qi * 8 + w];
            }
            sm->s_sum[qi] = a; sm->s_sumsq[qi] = b;
        }
        __syncthreads();
        const float mean = sm->s_sum[qi] * (1.0f / CDIM);
        const float var  = sm->s_sumsq[qi] * (1.0f / CDIM) - mean * mean;
        const float r    = rsqrtf(var + 1e-5f);
        out[(long)(qbase + qi) * CDIM + c] = (y - mean) * r * gamma[c] + beta[c];
    }
}

extern "C" void kernel_launch(void* const* d_in, const int* in_sizes, int n_in,
                              void* d_out, int out_size)
{
    // metadata order: res_feat, q_feat, k_feat, v_feat, q_pos, k_pos, gamma, beta
    // res_feat (d_in[0]) is mathematically dead: full scatter overwrite -> y = 2x.
    const float* q_feat = (const float*)d_in[1];
    const float* k_feat = (const float*)d_in[2];
    const float* v_feat = (const float*)d_in[3];
    const float* q_pos  = (const float*)d_in[4];
    const float* k_pos  = (const float*)d_in[5];
    const float* gamma  = (const float*)d_in[6];
    const float* beta   = (const float*)d_in[7];
    float* out = (float*)d_out;

    (void)in_sizes; (void)n_in; (void)out_size;

    cudaFuncSetAttribute(sparse_attn_kernel,
                         cudaFuncAttributeMaxDynamicSharedMemorySize,
                         (int)sizeof(Smem));
    sparse_attn_kernel<<<NQ / QB, NT, sizeof(Smem)>>>(
        q_feat, k_feat, v_feat, q_pos, k_pos, gamma, beta, out);
}

// round 6
// speedup vs baseline: 5.5403x; 1.1869x over previous
#include <cuda_runtime.h>
#include <cuda_bf16.h>
#include <math.h>

#define NKV   32768
#define NQ    4096
#define CDIM  256
#define KSEL  100
#define NT    512
#define QB    2
#define CAP   2048
#define SSAMP 2048   // sample size for threshold estimation
#define MSEL  32     // 32nd-smallest sample key -> threshold (upper bucket edge)

struct Smem {
    uint2    cand[QB][CAP];    // 32 KB {key, idx}; overlaid by sample keys first
    float4   part4[QB][256];   // 8 KB  AV partial sums (4 groups x 64 float4)
    float    qv[QB][CDIM];     // 2 KB
    float    attn[QB][128];    // 1 KB
    int      ids[QB][128];     // 1 KB
    unsigned hist[256];        // 1 KB
    int      warpsum[8];
    int      red_min[16];
    float    red1[16], red2[16];
    int      cnt_low[QB], cnt_c[QB];
    int      s_bucket, s_kneed, s_m;
    float    s_sum[QB], s_sumsq[QB];
};

// Canonical key pieces — identical fmaf chains everywhere => bit-identical keys.
__device__ __forceinline__ float k_sk(float kx, float ky, float kz) {
    return fmaf(kx, kx, fmaf(ky, ky, kz * kz));
}
__device__ __forceinline__ float k_dot(float kx, float ky, float kz,
                                       float qx, float qy, float qz) {
    return fmaf(qx, kx, fmaf(qy, ky, qz * kz));
}
__device__ __forceinline__ float k_d2u(float sk, float dot, float sqn) {
    return fmaf(-2.0f, dot, sqn + sk);      // unclamped
}
__device__ __forceinline__ unsigned k_key(float d2u) {
    return __float_as_uint(fmaxf(d2u, 0.0f));
}

// All 512 threads enter. Picks bucket containing the kcur-th smallest;
// results broadcast in sm->s_bucket / sm->s_kneed (valid after return).
__device__ __forceinline__ void pick_bucket(Smem* sm, int kcur, int tid, int lane) {
    int v = 0, incl = 0;
    if (tid < 256) {
        v = (int)sm->hist[tid];
        incl = v;
        #pragma unroll
        for (int o = 1; o < 32; o <<= 1) {
            int y = __shfl_up_sync(0xffffffffu, incl, o);
            if (lane >= o) incl += y;
        }
        if (lane == 31) sm->warpsum[tid >> 5] = incl;
    }
    __syncthreads();
    if (tid < 8) {
        int x = sm->warpsum[tid];
        #pragma unroll
        for (int o = 1; o < 8; o <<= 1) {
            int y = __shfl_up_sync(0xffu, x, o);
            if (tid >= o) x += y;
        }
        sm->warpsum[tid] = x;
    }
    __syncthreads();
    if (tid < 256) {
        const int w   = tid >> 5;
        const int tot = incl + (w ? sm->warpsum[w - 1] : 0);
        const int exc = tot - v;
        if (exc < kcur && tot >= kcur) {   // exactly one thread true
            sm->s_bucket = tid;
            sm->s_kneed  = kcur - exc;
        }
    }
    __syncthreads();
}

__global__ __launch_bounds__(NT, 4)
void sparse_attn_kernel(const float* __restrict__ q_feat,
                        const float* __restrict__ k_feat,
                        const float* __restrict__ v_feat,
                        const float* __restrict__ q_pos,
                        const float* __restrict__ k_pos,
                        const float* __restrict__ gamma,
                        const float* __restrict__ beta,
                        float* __restrict__ out)
{
    extern __shared__ unsigned char smem_raw[];
    Smem* sm = reinterpret_cast<Smem*>(smem_raw);
    const int tid  = threadIdx.x;
    const int lane = tid & 31;
    const int warp = tid >> 5;
    const int qbase = blockIdx.x * QB;
    const float4* __restrict__ kp4 = (const float4*)k_pos;   // packed [NKV*3/4]

    float qx[QB], qy[QB], qz[QB], sqn[QB];
    #pragma unroll
    for (int qi = 0; qi < QB; ++qi) {
        qx[qi] = q_pos[3 * (qbase + qi) + 0];
        qy[qi] = q_pos[3 * (qbase + qi) + 1];
        qz[qi] = q_pos[3 * (qbase + qi) + 2];
        sqn[qi] = fmaf(qx[qi], qx[qi], fmaf(qy[qi], qy[qi], qz[qi] * qz[qi]));
    }
    if (tid == 0) {
        sm->cnt_low[0] = sm->cnt_low[1] = 0;
        sm->cnt_c[0]   = sm->cnt_c[1]   = 0;
    }

    // ---------------- Phase 0: sample keys (first SSAMP points) -------------
    // SSAMP = 4*NT: each thread computes 4 points from 3 vector loads.
    unsigned* samp = (unsigned*)&sm->cand[0][0];   // SSAMP keys per query, overlaid
    {
        const float4 a = kp4[3 * tid + 0];
        const float4 b = kp4[3 * tid + 1];
        const float4 c = kp4[3 * tid + 2];
        const float s0 = k_sk(a.x, a.y, a.z);
        const float s1 = k_sk(a.w, b.x, b.y);
        const float s2 = k_sk(b.z, b.w, c.x);
        const float s3 = k_sk(c.y, c.z, c.w);
        #pragma unroll
        for (int qi = 0; qi < QB; ++qi) {
            uint4 kk;
            kk.x = k_key(k_d2u(s0, k_dot(a.x, a.y, a.z, qx[qi], qy[qi], qz[qi]), sqn[qi]));
            kk.y = k_key(k_d2u(s1, k_dot(a.w, b.x, b.y, qx[qi], qy[qi], qz[qi]), sqn[qi]));
            kk.z = k_key(k_d2u(s2, k_dot(b.z, b.w, c.x, qx[qi], qy[qi], qz[qi]), sqn[qi]));
            kk.w = k_key(k_d2u(s3, k_dot(c.y, c.z, c.w, qx[qi], qy[qi], qz[qi]), sqn[qi]));
            ((uint4*)samp)[qi * (SSAMP / 4) + tid] = kk;
        }
    }
    __syncthreads();

    // ---------------- Phase 1: 2-pass radix on samples -> threshold t0 ------
    // Upper edge of the 16-bit bucket of the MSEL-th smallest sample key.
    // Superset admission is always safe (exact refine + fallback below).
    float t0f[QB];
    #pragma unroll
    for (int qi = 0; qi < QB; ++qi) {
        unsigned prefval = 0u, prefmask = 0u;
        int kneed = MSEL;
        #pragma unroll
        for (int pass = 0; pass < 2; ++pass) {
            const int shift = 24 - 8 * pass;
            if (tid < 256) sm->hist[tid] = 0u;
            __syncthreads();
            #pragma unroll
            for (int it = 0; it < SSAMP / NT; ++it) {
                const unsigned key = samp[qi * SSAMP + tid + it * NT];
                const bool ok = ((key & prefmask) == prefval);
                const unsigned act = __ballot_sync(0xffffffffu, ok);
                if (ok) {
                    const unsigned b = (key >> shift) & 0xFFu;
                    const unsigned peers = __match_any_sync(act, b);
                    if ((__ffs(peers) - 1) == lane)
                        atomicAdd(&sm->hist[b], (unsigned)__popc(peers));
                }
            }
            __syncthreads();
            pick_bucket(sm, kneed, tid, lane);
            prefval  |= ((unsigned)sm->s_bucket) << shift;
            kneed     = sm->s_kneed;
            prefmask |= 0xFFu << shift;
            __syncthreads();
        }
        t0f[qi] = __uint_as_float(prefval | 0x0000FFFFu);   // bucket upper edge, finite, >= 0
    }
    __syncthreads();   // done reading samp; cand may now be written

    // ---------------- Phase 2: single full scan (4 points/thread/iter) ------
    // (clamped_key <= t0u) <=> (d2u <= t0f) since t0f >= 0.
    #pragma unroll 1
    for (int j = tid; j < NKV / 4; j += NT) {               // 16 iterations
        const float4 a = kp4[3 * j + 0];
        const float4 b = kp4[3 * j + 1];
        const float4 c = kp4[3 * j + 2];
        const float s0 = k_sk(a.x, a.y, a.z);
        const float s1 = k_sk(a.w, b.x, b.y);
        const float s2 = k_sk(b.z, b.w, c.x);
        const float s3 = k_sk(c.y, c.z, c.w);
        #pragma unroll
        for (int qi = 0; qi < QB; ++qi) {
            const float d0 = k_d2u(s0, k_dot(a.x, a.y, a.z, qx[qi], qy[qi], qz[qi]), sqn[qi]);
            const float d1 = k_d2u(s1, k_dot(a.w, b.x, b.y, qx[qi], qy[qi], qz[qi]), sqn[qi]);
            const float d2 = k_d2u(s2, k_dot(b.z, b.w, c.x, qx[qi], qy[qi], qz[qi]), sqn[qi]);
            const float d3 = k_d2u(s3, k_dot(c.y, c.z, c.w, qx[qi], qy[qi], qz[qi]), sqn[qi]);
            if (d0 <= t0f[qi]) {
                const int p = atomicAdd(&sm->cnt_c[qi], 1);
                if (p < CAP) sm->cand[qi][p] = make_uint2(k_key(d0), (unsigned)(4 * j + 0));
            }
            if (d1 <= t0f[qi]) {
                const int p = atomicAdd(&sm->cnt_c[qi], 1);
                if (p < CAP) sm->cand[qi][p] = make_uint2(k_key(d1), (unsigned)(4 * j + 1));
            }
            if (d2 <= t0f[qi]) {
                const int p = atomicAdd(&sm->cnt_c[qi], 1);
                if (p < CAP) sm->cand[qi][p] = make_uint2(k_key(d2), (unsigned)(4 * j + 2));
            }
            if (d3 <= t0f[qi]) {
                const int p = atomicAdd(&sm->cnt_c[qi], 1);
                if (p < CAP) sm->cand[qi][p] = make_uint2(k_key(d3), (unsigned)(4 * j + 3));
            }
        }
    }
    __syncthreads();

    // ---------------- Phase 3: exact top-KSEL per query ---------------------
    #pragma unroll
    for (int qi = 0; qi < QB; ++qi) {
        const int nc0 = sm->cnt_c[qi];
        unsigned T;
        int kneed;

        if (nc0 >= KSEL && nc0 <= CAP) {
            // ---- refine within <= CAP candidates: full 32-bit radix select --
            const int nc = nc0;
            unsigned prefval = 0u, prefmask = 0u;
            kneed = KSEL;
            #pragma unroll
            for (int pass = 0; pass < 4; ++pass) {
                const int shift = 24 - 8 * pass;
                if (tid < 256) sm->hist[tid] = 0u;
                __syncthreads();
                const int nIter = (nc + NT - 1) / NT;
                for (int it = 0; it < nIter; ++it) {
                    const int j = tid + it * NT;
                    const bool in = (j < nc);
                    const unsigned key = in ? sm->cand[qi][j].x : 0xffffffffu;
                    const bool ok = in && ((key & prefmask) == prefval);
                    const unsigned act = __ballot_sync(0xffffffffu, ok);
                    if (ok) {
                        const unsigned b = (key >> shift) & 0xFFu;
                        const unsigned peers = __match_any_sync(act, b);
                        if ((__ffs(peers) - 1) == lane)
                            atomicAdd(&sm->hist[b], (unsigned)__popc(peers));
                    }
                }
                __syncthreads();
                pick_bucket(sm, kneed, tid, lane);
                prefval  |= ((unsigned)sm->s_bucket) << shift;
                kneed     = sm->s_kneed;
                prefmask |= 0xFFu << shift;
                __syncthreads();
            }
            T = prefval;
            // strictly-less keys -> ids (order irrelevant: softmax perm-invariant)
            for (int j = tid; j < nc; j += NT) {
                const uint2 c = sm->cand[qi][j];
                if (c.x < T) {
                    const int p = atomicAdd(&sm->cnt_low[qi], 1);
                    sm->ids[qi][p] = (int)c.y;
                }
            }
            __syncthreads();
            // ties at T: kneed smallest indices (jax top_k stability)
            const int base = sm->cnt_low[qi];
            int last = -1;
            for (int t2 = 0; t2 < kneed; ++t2) {
                int local = 0x7fffffff;
                for (int j = tid; j < nc; j += NT) {
                    const uint2 c = sm->cand[qi][j];
                    if (c.x == T && (int)c.y > last) local = min(local, (int)c.y);
                }
                #pragma unroll
                for (int o = 16; o; o >>= 1)
                    local = min(local, __shfl_xor_sync(0xffffffffu, local, o));
                if (lane == 0) sm->red_min[warp] = local;
                __syncthreads();
                if (tid == 0) {
                    int m = 0x7fffffff;
                    #pragma unroll
                    for (int w = 0; w < NT / 32; ++w) m = min(m, sm->red_min[w]);
                    sm->ids[qi][base + t2] = m;
                    sm->s_m = m;
                }
                __syncthreads();
                last = sm->s_m;
                __syncthreads();
            }
        } else {
            // ---- fallback: exact full-rescan radix select (rare) ------------
            unsigned prefval = 0u, prefmask = 0u;
            kneed = KSEL;
            for (int pass = 0; pass < 4; ++pass) {
                const int shift = 24 - 8 * pass;
                if (tid < 256) sm->hist[tid] = 0u;
                __syncthreads();
                for (int i = tid; i < NKV; i += NT) {
                    const float kx = k_pos[3 * i + 0];
                    const float ky = k_pos[3 * i + 1];
                    const float kz = k_pos[3 * i + 2];
                    const unsigned key = k_key(k_d2u(k_sk(kx, ky, kz),
                                         k_dot(kx, ky, kz, qx[qi], qy[qi], qz[qi]), sqn[qi]));
                    const bool ok = ((key & prefmask) == prefval);
                    const unsigned act = __ballot_sync(0xffffffffu, ok);
                    if (ok) {
                        const unsigned b = (key >> shift) & 0xFFu;
                        const unsigned peers = __match_any_sync(act, b);
                        if ((__ffs(peers) - 1) == lane)
                            atomicAdd(&sm->hist[b], (unsigned)__popc(peers));
                    }
                }
                __syncthreads();
                pick_bucket(sm, kneed, tid, lane);
                prefval  |= ((unsigned)sm->s_bucket) << shift;
                kneed     = sm->s_kneed;
                prefmask |= 0xFFu << shift;
                __syncthreads();
            }
            T = prefval;
            if (tid == 0) sm->cnt_low[qi] = 0;
            __syncthreads();
            for (int i = tid; i < NKV; i += NT) {
                const float kx = k_pos[3 * i + 0];
                const float ky = k_pos[3 * i + 1];
                const float kz = k_pos[3 * i + 2];
                const unsigned key = k_key(k_d2u(k_sk(kx, ky, kz),
                                     k_dot(kx, ky, kz, qx[qi], qy[qi], qz[qi]), sqn[qi]));
                if (key < T) {
                    const int p = atomicAdd(&sm->cnt_low[qi], 1);
                    sm->ids[qi][p] = i;
                }
            }
            __syncthreads();
            const int base = sm->cnt_low[qi];
            int last = -1;
            for (int t2 = 0; t2 < kneed; ++t2) {
                int local = 0x7fffffff;
                for (int i = tid; i < NKV; i += NT) {
                    const float kx = k_pos[3 * i + 0];
                    const float ky = k_pos[3 * i + 1];
                    const float kz = k_pos[3 * i + 2];
                    const unsigned key = k_key(k_d2u(k_sk(kx, ky, kz),
                                         k_dot(kx, ky, kz, qx[qi], qy[qi], qz[qi]), sqn[qi]));
                    if (key == T && i > last) local = min(local, i);
                }
                #pragma unroll
                for (int o = 16; o; o >>= 1)
                    local = min(local, __shfl_xor_sync(0xffffffffu, local, o));
                if (lane == 0) sm->red_min[warp] = local;
                __syncthreads();
                if (tid == 0) {
                    int m = 0x7fffffff;
                    #pragma unroll
                    for (int w = 0; w < NT / 32; ++w) m = min(m, sm->red_min[w]);
                    sm->ids[qi][base + t2] = m;
                    sm->s_m = m;
                }
                __syncthreads();
                last = sm->s_m;
                __syncthreads();
            }
        }
        __syncthreads();
    }

    // ---------------- Phase 4: attention logits + softmax --------------------
    {
        const int qi = tid >> 8;
        const int c  = tid & 255;
        sm->qv[qi][c] = q_feat[(long)(qbase + qi) * CDIM + c];
    }
    __syncthreads();

    const int wq = warp >> 3;
    const int wl = warp & 7;
    for (int n = wl; n < KSEL; n += 8) {
        const float4* kr4 = (const float4*)(k_feat + (long)sm->ids[wq][n] * CDIM);
        const float4* qv4 = (const float4*)sm->qv[wq];
        float s = 0.f;
        #pragma unroll
        for (int c4 = lane; c4 < CDIM / 4; c4 += 32) {
            const float4 a = qv4[c4];
            const float4 b = kr4[c4];
            s = fmaf(a.x, b.x, s); s = fmaf(a.y, b.y, s);
            s = fmaf(a.z, b.z, s); s = fmaf(a.w, b.w, s);
        }
        #pragma unroll
        for (int o = 16; o; o >>= 1) s += __shfl_xor_sync(0xffffffffu, s, o);
        if (lane == 0) sm->attn[wq][n] = s * 0.0625f;   // C^-0.5 = 1/16
    }
    __syncthreads();

    if ((warp & 7) == 0) {              // warp 0 -> q0, warp 8 -> q1
        const int qi = wq;
        float m = -1e30f;
        for (int n = lane; n < KSEL; n += 32) m = fmaxf(m, sm->attn[qi][n]);
        #pragma unroll
        for (int o = 16; o; o >>= 1) m = fmaxf(m, __shfl_xor_sync(0xffffffffu, m, o));
        float ssum = 0.f;
        for (int n = lane; n < KSEL; n += 32) {
            const float e = __expf(sm->attn[qi][n] - m);
            sm->attn[qi][n] = e;
            ssum += e;
        }
        #pragma unroll
        for (int o = 16; o; o >>= 1) ssum += __shfl_xor_sync(0xffffffffu, ssum, o);
        const float inv = 1.f / ssum;
        for (int n = lane; n < KSEL; n += 32) sm->attn[qi][n] *= inv;
    }
    __syncthreads();

    // ---------------- Phase 5: x = attn @ V (float4, 4 groups/query) --------
    {
        const int qi = tid >> 8;           // query
        const int g  = (tid >> 6) & 3;     // group 0..3 (25 neighbors each)
        const int t  = tid & 63;           // 64 threads x float4 = 256 channels
        float4 acc = make_float4(0.f, 0.f, 0.f, 0.f);
        for (int n = g; n < KSEL; n += 4) {
            const float w  = sm->attn[qi][n];
            const float4 v4 = *(const float4*)(v_feat + (long)sm->ids[qi][n] * CDIM + t * 4);
            acc.x = fmaf(w, v4.x, acc.x);
            acc.y = fmaf(w, v4.y, acc.y);
            acc.z = fmaf(w, v4.z, acc.z);
            acc.w = fmaf(w, v4.w, acc.w);
        }
        sm->part4[qi][g * 64 + t] = acc;
    }
    __syncthreads();

    // ---------------- Phase 6: combine partials; y = 2x; LayerNorm ----------
    {
        const int qi = tid >> 8;
        const int c  = tid & 255;
        const float* pf = (const float*)&sm->part4[qi][0];
        const float y = 2.0f * ((pf[c] + pf[256 + c]) + (pf[512 + c] + pf[768 + c]));

        float s1 = y, s2 = y * y;
        #pragma unroll
        for (int o = 16; o; o >>= 1) {
            s1 += __shfl_xor_sync(0xffffffffu, s1, o);
            s2 += __shfl_xor_sync(0xffffffffu, s2, o);
        }
        if (lane == 0) { sm->red1[warp] = s1; sm->red2[warp] = s2; }
        __syncthreads();
        if ((tid & 255) == 0) {
            float a = 0.f, b = 0.f;
            #pragma unroll
            for (int w = 0; w < 8; ++w) {
                a += sm->red1[qi * 8 + w];
                b += sm->red2[qi * 8 + w];
            }
            sm->s_sum[qi] = a; sm->s_sumsq[qi] = b;
        }
        __syncthreads();
        const float mean = sm->s_sum[qi] * (1.0f / CDIM);
        const float var  = sm->s_sumsq[qi] * (1.0f / CDIM) - mean * mean;
        const float r    = rsqrtf(var + 1e-5f);
        out[(long)(qbase + qi) * CDIM + c] = (y - mean) * r * gamma[c] + beta[c];
    }
}

extern "C" void kernel_launch(void* const* d_in, const int* in_sizes, int n_in,
                              void* d_out, int out_size)
{
    // metadata order: res_feat, q_feat, k_feat, v_feat, q_pos, k_pos, gamma, beta
    // res_feat (d_in[0]) is mathematically dead: full scatter overwrite -> y = 2x.
    const float* q_feat = (const float*)d_in[1];
    const float* k_feat = (const float*)d_in[2];
    const float* v_feat = (const float*)d_in[3];
    const float* q_pos  = (const float*)d_in[4];
    const float* k_pos  = (const float*)d_in[5];
    const float* gamma  = (const float*)d_in[6];
    const float* beta   = (const float*)d_in[7];
    float* out = (float*)d_out;

    (void)in_sizes; (void)n_in; (void)out_size;

    cudaFuncSetAttribute(sparse_attn_kernel,
                         cudaFuncAttributeMaxDynamicSharedMemorySize,
                         (int)sizeof(Smem));
    sparse_attn_kernel<<<NQ / QB, NT, sizeof(Smem)>>>(
        q_feat, k_feat, v_feat, q_pos, k_pos, gamma, beta, out);
}